// round 7
// baseline (speedup 1.0000x reference)
#include <cuda_runtime.h>
#include <cuda_bf16.h>
#include <cstdint>

// out = x @ Weff + bias;  Weff[8m+p, f] = sum_k scale[k,f]*sign(bit(7-p) of binary[k,m,f])
// Fully fused: each GEMM CTA builds its own bf16-split tiles (Ah/Al from x,
// Bh/Bl from binary*scale) in smem, runs HMMA with fused 3-segment accumulate
// (Ah*Bh + Al*Bh + Ah*Bl), writes split-K partials; tiny reduce adds bias.

#define NX 768
#define NF 768
#define NM 256
#define NG 96

#define SPLITS 6
#define BKC 128          // k per CTA
#define ROWP 136         // 128 + 8 halves pad -> conflict-free ldmatrix

__device__ float g_part[SPLITS * NM * NF];

// ---------------------------------------------------------------------------
union B2U { __nv_bfloat162 h2; uint32_t u; };
__device__ __forceinline__ uint32_t pk2(__nv_bfloat16 a, __nv_bfloat16 b) {
    B2U t; t.h2 = __halves2bfloat162(a, b); return t.u;
}
__device__ __forceinline__ uint32_t smem_u32(const void* p) {
    uint32_t a;
    asm("{ .reg .u64 t; cvta.to.shared.u64 t, %1; cvt.u32.u64 %0, t; }"
        : "=r"(a) : "l"(p));
    return a;
}

#define LDSM4(r, addr) \
    asm volatile("ldmatrix.sync.aligned.m8n8.x4.shared.b16 {%0,%1,%2,%3}, [%4];" \
                 : "=r"((r)[0]), "=r"((r)[1]), "=r"((r)[2]), "=r"((r)[3]) : "r"(addr))

#define MMA16816(c, a, bb0, bb1) \
    asm volatile("mma.sync.aligned.m16n8k16.row.col.f32.bf16.bf16.f32 " \
                 "{%0,%1,%2,%3}, {%4,%5,%6,%7}, {%8,%9}, {%0,%1,%2,%3};" \
                 : "+f"((c)[0]), "+f"((c)[1]), "+f"((c)[2]), "+f"((c)[3]) \
                 : "r"((a)[0]), "r"((a)[1]), "r"((a)[2]), "r"((a)[3]), \
                   "r"(bb0), "r"(bb1))

// ---------------------------------------------------------------------------
// Fused GEMM. Grid (12 n, 4 m, 6 split) = 288 CTAs x 256 thr.
// Tile: 64(m) x 64(f) x 128(k). Smem: AH/AL/BH/BL, each 64 x ROWP bf16.
// ---------------------------------------------------------------------------
#define SM_T (64 * ROWP)
#define SMEM_BYTES (4 * SM_T * 2)    // 69632

__global__ __launch_bounds__(256)
void gemm_fused_kernel(const float* __restrict__ x,
                       const float* __restrict__ scale,
                       const int*   __restrict__ binary) {
    extern __shared__ __align__(16) __nv_bfloat16 sm[];
    __nv_bfloat16* AH = sm;
    __nv_bfloat16* AL = sm + SM_T;
    __nv_bfloat16* BH = sm + 2 * SM_T;
    __nv_bfloat16* BL = sm + 3 * SM_T;

    const int tid  = threadIdx.x;
    const int wid  = tid >> 5;
    const int lane = tid & 31;

    const int f0 = blockIdx.x * 64;
    const int m0 = blockIdx.y * 64;
    const int k0 = blockIdx.z * BKC;
    const int g0 = k0 >> 3;            // first weight-group of this k-chunk

    // ---------------- build A tiles (x -> Ah/Al) ----------------
    // thread: row r = tid>>2 (0..63), seg = tid&3 (32 floats each)
    {
        const int r   = tid >> 2;
        const int seg = tid & 3;
        const float* gx = x + (size_t)(m0 + r) * NX + k0 + seg * 32;
        float4 v[8];
#pragma unroll
        for (int j = 0; j < 8; j++) v[j] = ((const float4*)gx)[j];

        uint4* dh = (uint4*)(AH + r * ROWP + seg * 32);
        uint4* dl = (uint4*)(AL + r * ROWP + seg * 32);
#pragma unroll
        for (int j = 0; j < 8; j += 2) {
            __nv_bfloat16 h[8], l[8];
#pragma unroll
            for (int u = 0; u < 2; u++) {
                float4 w = v[j + u];
                h[u*4+0] = __float2bfloat16(w.x); h[u*4+1] = __float2bfloat16(w.y);
                h[u*4+2] = __float2bfloat16(w.z); h[u*4+3] = __float2bfloat16(w.w);
                l[u*4+0] = __float2bfloat16(w.x - __bfloat162float(h[u*4+0]));
                l[u*4+1] = __float2bfloat16(w.y - __bfloat162float(h[u*4+1]));
                l[u*4+2] = __float2bfloat16(w.z - __bfloat162float(h[u*4+2]));
                l[u*4+3] = __float2bfloat16(w.w - __bfloat162float(h[u*4+3]));
            }
            dh[j >> 1] = make_uint4(pk2(h[0], h[1]), pk2(h[2], h[3]),
                                    pk2(h[4], h[5]), pk2(h[6], h[7]));
            dl[j >> 1] = make_uint4(pk2(l[0], l[1]), pk2(l[2], l[3]),
                                    pk2(l[4], l[5]), pk2(l[6], l[7]));
        }
    }

    // ---------------- build B tiles (binary*scale -> Bh/Bl) ----------------
    // thread: feature f = tid&63, groups mg = (tid>>6) + {0,4,8,12}
    {
        const int fl = tid & 63;
        const int mgb = tid >> 6;          // 0..3
        const int f  = f0 + fl;

        float s[8];
#pragma unroll
        for (int k = 0; k < 8; k++) s[k] = scale[k * NF + f];

        int c[4][8];
#pragma unroll
        for (int j = 0; j < 4; j++) {
            const int mg = g0 + mgb + 4 * j;
#pragma unroll
            for (int k = 0; k < 8; k++)
                c[j][k] = binary[(size_t)(k * NG + mg) * NF + f];
        }

#pragma unroll
        for (int j = 0; j < 4; j++) {
            float w[8];
#pragma unroll
            for (int p = 0; p < 8; p++) w[p] = 0.0f;
#pragma unroll
            for (int k = 0; k < 8; k++)
#pragma unroll
                for (int p = 0; p < 8; p++)
                    w[p] += ((c[j][k] >> (7 - p)) & 1) ? s[k] : -s[k];

            __nv_bfloat16 hi[8], lo[8];
#pragma unroll
            for (int p = 0; p < 8; p++) {
                hi[p] = __float2bfloat16(w[p]);
                lo[p] = __float2bfloat16(w[p] - __bfloat162float(hi[p]));
            }
            const int kc = (mgb + 4 * j) * 8;   // k-offset within chunk
            *(uint4*)(BH + fl * ROWP + kc) =
                make_uint4(pk2(hi[0], hi[1]), pk2(hi[2], hi[3]),
                           pk2(hi[4], hi[5]), pk2(hi[6], hi[7]));
            *(uint4*)(BL + fl * ROWP + kc) =
                make_uint4(pk2(lo[0], lo[1]), pk2(lo[2], lo[3]),
                           pk2(lo[4], lo[5]), pk2(lo[6], lo[7]));
        }
    }

    __syncthreads();

    // ---------------- HMMA mainloop ----------------
    const int wm = (wid >> 1) * 16;   // 4 warps along m
    const int wn = (wid & 1) * 32;    // 2 warps along n

    float acc[4][4];
#pragma unroll
    for (int j = 0; j < 4; j++)
#pragma unroll
        for (int v = 0; v < 4; v++) acc[j][v] = 0.0f;

    const int ra  = wm + (lane & 15);
    const int rb0 = wn + (lane & 15);
    const uint32_t smb = smem_u32(sm);

#pragma unroll
    for (int ks = 0; ks < 8; ks++) {
        const int c = ks * 16 + ((lane >> 4) << 3);
        uint32_t ah[4], al[4], bh0[4], bh1[4], bl0[4], bl1[4];
        LDSM4(ah,  smb + (uint32_t)(ra * ROWP + c) * 2);
        LDSM4(al,  smb + (uint32_t)(SM_T + ra * ROWP + c) * 2);
        LDSM4(bh0, smb + (uint32_t)(2 * SM_T + rb0 * ROWP + c) * 2);
        LDSM4(bh1, smb + (uint32_t)(2 * SM_T + (rb0 + 16) * ROWP + c) * 2);
        LDSM4(bl0, smb + (uint32_t)(3 * SM_T + rb0 * ROWP + c) * 2);
        LDSM4(bl1, smb + (uint32_t)(3 * SM_T + (rb0 + 16) * ROWP + c) * 2);

        MMA16816(acc[0], ah, bh0[0], bh0[2]);
        MMA16816(acc[1], ah, bh0[1], bh0[3]);
        MMA16816(acc[2], ah, bh1[0], bh1[2]);
        MMA16816(acc[3], ah, bh1[1], bh1[3]);

        MMA16816(acc[0], al, bh0[0], bh0[2]);
        MMA16816(acc[1], al, bh0[1], bh0[3]);
        MMA16816(acc[2], al, bh1[0], bh1[2]);
        MMA16816(acc[3], al, bh1[1], bh1[3]);

        MMA16816(acc[0], ah, bl0[0], bl0[2]);
        MMA16816(acc[1], ah, bl0[1], bl0[3]);
        MMA16816(acc[2], ah, bl1[0], bl1[2]);
        MMA16816(acc[3], ah, bl1[1], bl1[3]);
    }

    // ---------------- store split-K partials ----------------
    float* P = g_part + (size_t)blockIdx.z * (NM * NF);
    const int rbase = m0 + wm + (lane >> 2);
    const int cbase = f0 + wn + (lane & 3) * 2;
#pragma unroll
    for (int ni = 0; ni < 4; ni++) {
        int col = cbase + ni * 8;
        *(float2*)(P + (size_t)rbase * NF + col)       = make_float2(acc[ni][0], acc[ni][1]);
        *(float2*)(P + (size_t)(rbase + 8) * NF + col) = make_float2(acc[ni][2], acc[ni][3]);
    }
}

// ---------------------------------------------------------------------------
// Reduce 6 partials + bias -> out. 49152 float4 lanes.
// ---------------------------------------------------------------------------
__global__ __launch_bounds__(256)
void reduce_kernel(const float* __restrict__ bias, float* __restrict__ out) {
    const int idx = blockIdx.x * 256 + threadIdx.x;
    float4 p[SPLITS];
#pragma unroll
    for (int s = 0; s < SPLITS; s++)
        p[s] = ((const float4*)g_part)[s * (NM * NF / 4) + idx];
    float4 v = ((const float4*)bias)[idx % (NF / 4)];
#pragma unroll
    for (int s = 0; s < SPLITS; s++) {
        v.x += p[s].x; v.y += p[s].y; v.z += p[s].z; v.w += p[s].w;
    }
    ((float4*)out)[idx] = v;
}

// ---------------------------------------------------------------------------
extern "C" void kernel_launch(void* const* d_in, const int* in_sizes, int n_in,
                              void* d_out, int out_size) {
    const float* x      = (const float*)d_in[0];
    const float* scale  = (const float*)d_in[1];
    const int*   binary = (const int*)  d_in[2];
    const float* bias   = (const float*)d_in[3];
    float*       out    = (float*)d_out;

    cudaFuncSetAttribute(gemm_fused_kernel,
                         cudaFuncAttributeMaxDynamicSharedMemorySize, SMEM_BYTES);

    dim3 grid(NF / 64, NM / 64, SPLITS);   // 12 x 4 x 6 = 288 CTAs
    gemm_fused_kernel<<<grid, 256, SMEM_BYTES>>>(x, scale, binary);

    reduce_kernel<<<NM * NF / 4 / 256, 256>>>(bias, out);
}